// round 3
// baseline (speedup 1.0000x reference)
#include <cuda_runtime.h>
#include <cstdint>

#define Bq    4
#define Nq    2048
#define DINq  256
#define DOUTq 256
#define Hq    4
#define HDq   64
#define NEG_SLOPE 0.2f

// ---------------- scratch (no allocation allowed) ----------------
__device__ float g_h[Bq * Nq * DOUTq];       // 8 MB: h = x @ W^T
__device__ float g_ssrc[Bq * Nq * Hq];
__device__ float g_sdst[Bq * Nq * Hq];
__device__ float g_linv[Bq * Nq * Hq];       // per-(row,head) 1/sum(exp)

// ---------------- packed f32x2 helpers ----------------
__device__ __forceinline__ void ffma2(unsigned long long& acc,
                                      unsigned long long p,
                                      unsigned long long h) {
    asm("fma.rn.f32x2 %0, %1, %2, %0;" : "+l"(acc) : "l"(p), "l"(h));
}
__device__ __forceinline__ unsigned long long pack2(float lo, float hi) {
    unsigned long long r;
    asm("mov.b64 %0, {%1, %2};" : "=l"(r) : "f"(lo), "f"(hi));
    return r;
}
__device__ __forceinline__ void unpack2(unsigned long long v, float& lo, float& hi) {
    asm("mov.b64 {%0, %1}, %2;" : "=f"(lo), "=f"(hi) : "l"(v));
}

// =====================================================================
// Kernel 1: h[row, d] = sum_k x[row, k] * W[d, k]
// =====================================================================
__global__ __launch_bounds__(256) void gemm_xWT_kernel(const float* __restrict__ x,
                                                       const float* __restrict__ W) {
    __shared__ float as[16][68];
    __shared__ float bs[16][68];

    const int tid = threadIdx.x;
    const int tx = tid & 15, ty = tid >> 4;
    const int row0 = blockIdx.x * 64;
    const int col0 = blockIdx.y * 64;

    float acc[4][4] = {};

    const int lr = tid >> 2;
    const int lq = (tid & 3) * 4;
    const float* xp = x + (size_t)(row0 + lr) * DINq + lq;
    const float* wp = W + (size_t)(col0 + lr) * DINq + lq;

    for (int kc = 0; kc < DINq; kc += 16) {
        float4 v  = *(const float4*)(xp + kc);
        float4 wv = *(const float4*)(wp + kc);
        as[lq + 0][lr] = v.x;  as[lq + 1][lr] = v.y;
        as[lq + 2][lr] = v.z;  as[lq + 3][lr] = v.w;
        bs[lq + 0][lr] = wv.x; bs[lq + 1][lr] = wv.y;
        bs[lq + 2][lr] = wv.z; bs[lq + 3][lr] = wv.w;
        __syncthreads();

#pragma unroll
        for (int k = 0; k < 16; k++) {
            float a4[4], b4[4];
            *(float4*)a4 = *(const float4*)&as[k][ty * 4];
            *(float4*)b4 = *(const float4*)&bs[k][tx * 4];
#pragma unroll
            for (int i = 0; i < 4; i++)
#pragma unroll
                for (int j = 0; j < 4; j++)
                    acc[i][j] += a4[i] * b4[j];
        }
        __syncthreads();
    }

#pragma unroll
    for (int i = 0; i < 4; i++) {
        float4 o;
        o.x = acc[i][0]; o.y = acc[i][1]; o.z = acc[i][2]; o.w = acc[i][3];
        *(float4*)&g_h[(size_t)(row0 + ty * 4 + i) * DOUTq + col0 + tx * 4] = o;
    }
}

// =====================================================================
// Kernel 2: per-(row,head) scores via warp dot products
// =====================================================================
__global__ __launch_bounds__(256) void score_kernel(const float* __restrict__ a_src,
                                                    const float* __restrict__ a_dst) {
    const int task = blockIdx.x * 8 + (threadIdx.x >> 5);   // row*4 + head
    const int ln = threadIdx.x & 31;
    const int row = task >> 2;
    const int head = task & 3;

    const float* hp = g_h + (size_t)row * DOUTq + head * HDq;
    float v0 = hp[ln], v1 = hp[ln + 32];
    float s1 = v0 * a_src[head * HDq + ln] + v1 * a_src[head * HDq + ln + 32];
    float s2 = v0 * a_dst[head * HDq + ln] + v1 * a_dst[head * HDq + ln + 32];
#pragma unroll
    for (int off = 16; off > 0; off >>= 1) {
        s1 += __shfl_xor_sync(0xFFFFFFFFu, s1, off);
        s2 += __shfl_xor_sync(0xFFFFFFFFu, s2, off);
    }
    if (ln == 0) {
        g_ssrc[task] = s1;
        g_sdst[task] = s2;
    }
}

// =====================================================================
// Kernel 3: single-pass softmax denominator (no max subtraction: |e| is
// small — scores are O(1) dot products — so exp() is safely in fp32 range).
//   linv[b,i,h] = 1 / sum_j adj[b,i,j] ? exp(leaky(s_src+s_dst)) : 0
// =====================================================================
__global__ __launch_bounds__(128) void stats_kernel(const float* __restrict__ adj) {
    const int b = blockIdx.y;
    const int i = blockIdx.x;
    const int row = b * Nq + i;
    const float* arow = adj + (size_t)row * Nq;

    float4 ss4 = *(const float4*)&g_ssrc[row * 4];
    const float ss[4] = {ss4.x, ss4.y, ss4.z, ss4.w};

    float lloc[4] = {0.f, 0.f, 0.f, 0.f};
    for (int j = threadIdx.x; j < Nq; j += 128) {
        float a = arow[j];
        if (a != 0.0f) {
            float4 sd = *(const float4*)&g_sdst[(b * Nq + j) * 4];
            float e0 = ss[0] + sd.x; e0 = e0 > 0.f ? e0 : NEG_SLOPE * e0;
            float e1 = ss[1] + sd.y; e1 = e1 > 0.f ? e1 : NEG_SLOPE * e1;
            float e2 = ss[2] + sd.z; e2 = e2 > 0.f ? e2 : NEG_SLOPE * e2;
            float e3 = ss[3] + sd.w; e3 = e3 > 0.f ? e3 : NEG_SLOPE * e3;
            lloc[0] += __expf(e0); lloc[1] += __expf(e1);
            lloc[2] += __expf(e2); lloc[3] += __expf(e3);
        }
    }
#pragma unroll
    for (int off = 16; off > 0; off >>= 1)
#pragma unroll
        for (int h = 0; h < 4; h++)
            lloc[h] += __shfl_xor_sync(0xFFFFFFFFu, lloc[h], off);

    __shared__ float red[4][4];
    const int w = threadIdx.x >> 5, ln = threadIdx.x & 31;
    if (ln == 0)
#pragma unroll
        for (int h = 0; h < 4; h++) red[h][w] = lloc[h];
    __syncthreads();

    if (threadIdx.x == 0) {
#pragma unroll
        for (int h = 0; h < 4; h++) {
            float l = red[h][0] + red[h][1] + red[h][2] + red[h][3];
            g_linv[row * 4 + h] = 1.0f / l;
        }
    }
}

// =====================================================================
// Kernel 4: fused aggregation.
//   out[b, i, d] = sum_j alpha[b,i,j,head(d)] * h[b, j, d]
// TI=32 rows of i, TJ=32 cols of j per tile. 256 threads:
//   half = t>>7 selects ti range [16*half, 16*half+16)
//   g = t&127 owns output columns (2g, 2g+1)  -> float2 LDG of h
// Per jj per thread: 4 broadcast LDS.128 of alpha + 1 LDG.64 + 16 FFMA2.
// =====================================================================
#define TI 32
#define TJ 32

__global__ __launch_bounds__(256, 4) void agg_kernel(const float* __restrict__ adj,
                                                     float* __restrict__ out) {
    __shared__ __align__(16) float sp[TJ * Hq * TI];   // [jj][head][ti]  16 KB
    __shared__ float sadjT[TJ][TI + 1];                // [jj][ti] padded, 4.1 KB
    __shared__ float ssd[TJ * Hq];                     // s_dst tile
    __shared__ float s_src_s[Hq][TI];
    __shared__ float s_li[Hq][TI];

    const int t = threadIdx.x;
    const int g = t & 127;
    const int half = t >> 7;
    const int tib = half * 16;
    const int head = g >> 5;
    const int c0 = 2 * g;
    const int b = blockIdx.y;
    const int i0 = blockIdx.x * TI;
    const int rowb = b * Nq + i0;

    if (t < TI) {
        float4 v = *(const float4*)&g_ssrc[(rowb + t) * 4];
        s_src_s[0][t] = v.x; s_src_s[1][t] = v.y; s_src_s[2][t] = v.z; s_src_s[3][t] = v.w;
        v = *(const float4*)&g_linv[(rowb + t) * 4];
        s_li[0][t] = v.x; s_li[1][t] = v.y; s_li[2][t] = v.z; s_li[3][t] = v.w;
    }

    unsigned long long accA[8], accB[8];
#pragma unroll
    for (int q = 0; q < 8; q++) { accA[q] = 0ull; accB[q] = 0ull; }

    for (int jt = 0; jt < Nq / TJ; jt++) {
        const int j0 = jt * TJ;

        // ---- load adj tile (coalesced: consecutive t -> consecutive jj) ----
#pragma unroll
        for (int r = 0; r < 4; r++) {
            int idx = t + r * 256;
            int ti = idx >> 5, jj = idx & 31;
            sadjT[jj][ti] = adj[(size_t)(rowb + ti) * Nq + j0 + jj];
        }
        if (t < TJ * Hq) ssd[t] = g_sdst[(b * Nq + j0) * 4 + t];
        __syncthreads();

        // ---- compute alpha tile: sp[jj][hh][ti] ----
#pragma unroll
        for (int r = 0; r < 16; r++) {
            int idx = t + r * 256;            // = jj*128 + hh*32 + ti
            int jj = idx >> 7;
            int hh = (idx >> 5) & 3;
            int ti = idx & 31;
            float a = sadjT[jj][ti];
            float p = 0.0f;
            if (a != 0.0f) {
                float e = s_src_s[hh][ti] + ssd[jj * 4 + hh];
                e = e > 0.f ? e : NEG_SLOPE * e;
                p = __expf(e) * s_li[hh][ti];
            }
            sp[idx] = p;
        }
        __syncthreads();

        // ---- rank-TJ update: 2 columns (c0, c0+1), 16 i-rows each ----
        const float* hrow = g_h + (size_t)(b * Nq + j0) * DOUTq + c0;
#pragma unroll 4
        for (int jj = 0; jj < TJ; jj++) {
            float2 hv = *(const float2*)(hrow + jj * DOUTq);
            unsigned long long h0 = pack2(hv.x, hv.x);
            unsigned long long h1 = pack2(hv.y, hv.y);
            const uint4* pp = (const uint4*)(sp + jj * 128 + head * 32 + tib);
#pragma unroll
            for (int q = 0; q < 4; q++) {
                uint4 pv = pp[q];
                unsigned long long p01 = pack2(__uint_as_float(pv.x), __uint_as_float(pv.y));
                unsigned long long p23 = pack2(__uint_as_float(pv.z), __uint_as_float(pv.w));
                ffma2(accA[q * 2 + 0], p01, h0);
                ffma2(accA[q * 2 + 1], p23, h0);
                ffma2(accB[q * 2 + 0], p01, h1);
                ffma2(accB[q * 2 + 1], p23, h1);
            }
        }
        __syncthreads();
    }

    // ---- epilogue: accA[e] = col c0, accB[e] = col c0+1, ti pairs ----
#pragma unroll
    for (int e = 0; e < 8; e++) {
        float a_lo, a_hi, b_lo, b_hi;
        unpack2(accA[e], a_lo, a_hi);
        unpack2(accB[e], b_lo, b_hi);
        int ti0 = tib + 4 * (e >> 1) + 2 * (e & 1);
        float2 o0; o0.x = a_lo; o0.y = b_lo;
        float2 o1; o1.x = a_hi; o1.y = b_hi;
        *(float2*)&out[(size_t)(rowb + ti0 + 0) * DOUTq + c0] = o0;
        *(float2*)&out[(size_t)(rowb + ti0 + 1) * DOUTq + c0] = o1;
    }
}

// =====================================================================
extern "C" void kernel_launch(void* const* d_in, const int* in_sizes, int n_in,
                              void* d_out, int out_size) {
    const float* x     = (const float*)d_in[0];   // [B,N,DIN]
    const float* adj   = (const float*)d_in[1];   // [B,N,N]
    const float* W     = (const float*)d_in[2];   // [DOUT,DIN]
    const float* a_src = (const float*)d_in[3];   // [H,HD]
    const float* a_dst = (const float*)d_in[4];   // [H,HD]
    float* out = (float*)d_out;                   // [B,N,DOUT]

    gemm_xWT_kernel<<<dim3((Bq * Nq) / 64, DOUTq / 64), 256>>>(x, W);
    score_kernel<<<(Bq * Nq * Hq) / 8, 256>>>(a_src, a_dst);
    stats_kernel<<<dim3(Nq, Bq), 128>>>(adj);
    agg_kernel<<<dim3(Nq / TI, Bq), 256>>>(adj, out);
}

// round 4
// speedup vs baseline: 1.4678x; 1.4678x over previous
#include <cuda_runtime.h>
#include <cstdint>

#define Bq    4
#define Nq    2048
#define DINq  256
#define DOUTq 256
#define Hq    4
#define HDq   64
#define NEG_SLOPE 0.2f

// ---------------- scratch (no allocation allowed) ----------------
__device__ float g_h[Bq * Nq * DOUTq];       // 8 MB: h = x @ W^T
__device__ float g_ssrc[Bq * Nq * Hq];
__device__ float g_sdst[Bq * Nq * Hq];

// ---------------- packed f32x2 helpers ----------------
__device__ __forceinline__ void ffma2(unsigned long long& acc,
                                      unsigned long long p,
                                      unsigned long long h) {
    asm("fma.rn.f32x2 %0, %1, %2, %0;" : "+l"(acc) : "l"(p), "l"(h));
}
__device__ __forceinline__ unsigned long long pack2(float lo, float hi) {
    unsigned long long r;
    asm("mov.b64 %0, {%1, %2};" : "=l"(r) : "f"(lo), "f"(hi));
    return r;
}
__device__ __forceinline__ void unpack2(unsigned long long v, float& lo, float& hi) {
    asm("mov.b64 {%0, %1}, %2;" : "=f"(lo), "=f"(hi) : "l"(v));
}

// =====================================================================
// Kernel 1: h = x @ W^T.  128x64 tile, 256 threads, 8x4 micro-tile with
// packed f32x2 accumulators (rows packed in pairs).
// =====================================================================
__global__ __launch_bounds__(256) void gemm_xWT_kernel(const float* __restrict__ x,
                                                       const float* __restrict__ W) {
    __shared__ float as[16][132];   // [k][row 0..127]
    __shared__ float bs[16][68];    // [k][col 0..63]

    const int tid = threadIdx.x;
    const int tx = tid & 15;        // col group (4 cols)
    const int ty = tid >> 4;        // row group (8 rows)
    const int row0 = blockIdx.x * 128;
    const int col0 = blockIdx.y * 64;

    unsigned long long acc2[4][4];
#pragma unroll
    for (int i = 0; i < 4; i++)
#pragma unroll
        for (int j = 0; j < 4; j++) acc2[i][j] = 0ull;

    const int arow = tid >> 1;           // 0..127
    const int aq   = (tid & 1) * 8;      // 0 or 8
    const int brow = tid >> 2;           // 0..63
    const int bq   = (tid & 3) * 4;      // 0,4,8,12
    const float* xp = x + (size_t)(row0 + arow) * DINq + aq;
    const float* wp = W + (size_t)(col0 + brow) * DINq + bq;

    for (int kc = 0; kc < DINq; kc += 16) {
        float4 v0 = *(const float4*)(xp + kc);
        float4 v1 = *(const float4*)(xp + kc + 4);
        float4 wv = *(const float4*)(wp + kc);
        as[aq + 0][arow] = v0.x; as[aq + 1][arow] = v0.y;
        as[aq + 2][arow] = v0.z; as[aq + 3][arow] = v0.w;
        as[aq + 4][arow] = v1.x; as[aq + 5][arow] = v1.y;
        as[aq + 6][arow] = v1.z; as[aq + 7][arow] = v1.w;
        bs[bq + 0][brow] = wv.x; bs[bq + 1][brow] = wv.y;
        bs[bq + 2][brow] = wv.z; bs[bq + 3][brow] = wv.w;
        __syncthreads();

#pragma unroll
        for (int k = 0; k < 16; k++) {
            float a8[8], b4[4];
            *(float4*)a8       = *(const float4*)&as[k][ty * 8];
            *(float4*)(a8 + 4) = *(const float4*)&as[k][ty * 8 + 4];
            *(float4*)b4       = *(const float4*)&bs[k][tx * 4];
            unsigned long long bp[4];
#pragma unroll
            for (int j = 0; j < 4; j++) bp[j] = pack2(b4[j], b4[j]);
#pragma unroll
            for (int i = 0; i < 4; i++) {
                unsigned long long ap = pack2(a8[2 * i], a8[2 * i + 1]);
#pragma unroll
                for (int j = 0; j < 4; j++) ffma2(acc2[i][j], ap, bp[j]);
            }
        }
        __syncthreads();
    }

#pragma unroll
    for (int i = 0; i < 4; i++) {
        float lo[4], hi[4];
#pragma unroll
        for (int j = 0; j < 4; j++) unpack2(acc2[i][j], lo[j], hi[j]);
        float4 o0; o0.x = lo[0]; o0.y = lo[1]; o0.z = lo[2]; o0.w = lo[3];
        float4 o1; o1.x = hi[0]; o1.y = hi[1]; o1.z = hi[2]; o1.w = hi[3];
        const int r = row0 + ty * 8 + 2 * i;
        *(float4*)&g_h[(size_t)(r + 0) * DOUTq + col0 + tx * 4] = o0;
        *(float4*)&g_h[(size_t)(r + 1) * DOUTq + col0 + tx * 4] = o1;
    }
}

// =====================================================================
// Kernel 2: per-(row,head) scores via warp dot products
// =====================================================================
__global__ __launch_bounds__(256) void score_kernel(const float* __restrict__ a_src,
                                                    const float* __restrict__ a_dst) {
    const int task = blockIdx.x * 8 + (threadIdx.x >> 5);   // row*4 + head
    const int ln = threadIdx.x & 31;
    const int row = task >> 2;
    const int head = task & 3;

    const float* hp = g_h + (size_t)row * DOUTq + head * HDq;
    float v0 = hp[ln], v1 = hp[ln + 32];
    float s1 = v0 * a_src[head * HDq + ln] + v1 * a_src[head * HDq + ln + 32];
    float s2 = v0 * a_dst[head * HDq + ln] + v1 * a_dst[head * HDq + ln + 32];
#pragma unroll
    for (int off = 16; off > 0; off >>= 1) {
        s1 += __shfl_xor_sync(0xFFFFFFFFu, s1, off);
        s2 += __shfl_xor_sync(0xFFFFFFFFu, s2, off);
    }
    if (ln == 0) {
        g_ssrc[task] = s1;
        g_sdst[task] = s2;
    }
}

// =====================================================================
// Kernel 3: fused aggregation + inline softmax denominator.
//   out[b,i,d] = (1/l[i,h]) * sum_j adj * exp(leaky(ssrc_i + sdst_j)) * h[j,d]
// Block: TI=16 i-rows, all 256 cols. 8 warps; warp w owns head=w&3,
// ti-half=(w>>2)*8 — its alpha strip is consumed only by itself, so the
// main loop is completely __syncthreads-free (only __syncwarp).
// Thread owns cols (c0, c0+1); 8 packed f32x2 accumulators.
// Lane = jj within the 32-wide j tile; adj + s_dst live in registers.
// =====================================================================
#define TI 16
#define TJ 32

__global__ __launch_bounds__(256, 3) void agg_kernel(const float* __restrict__ adj,
                                                     float* __restrict__ out) {
    __shared__ __align__(16) float pw[8][TJ * 8];   // per-warp alpha [jj][ti8], 8 KB

    const int t = threadIdx.x;
    const int w = t >> 5;
    const int lane = t & 31;
    const int head = w & 3;
    const int tib = (w >> 2) * 8;       // 0 or 8
    const int g = t & 127;
    const int c0 = 2 * g;               // this thread's 2 output cols
    const int b = blockIdx.y;
    const int i0 = blockIdx.x * TI;
    const int rowb = b * Nq + i0;
    const int bN = b * Nq;

    float* pwme = &pw[w][0];

    float ssrc_r[8];
#pragma unroll
    for (int r = 0; r < 8; r++)
        ssrc_r[r] = g_ssrc[(size_t)(rowb + tib + r) * 4 + head];

    unsigned long long accA[4], accB[4];
#pragma unroll
    for (int q = 0; q < 4; q++) { accA[q] = 0ull; accB[q] = 0ull; }
    float lsum[8];
#pragma unroll
    for (int r = 0; r < 8; r++) lsum[r] = 0.f;

    const float* adjbase = adj + (size_t)(rowb + tib) * Nq;

    // prologue loads for jt = 0
    float av[8], sd;
    sd = __ldg(&g_sdst[(size_t)(bN + lane) * 4 + head]);
#pragma unroll
    for (int r = 0; r < 8; r++)
        av[r] = __ldg(adjbase + (size_t)r * Nq + lane);

    for (int jt = 0; jt < Nq / TJ; jt++) {
        const int j0 = jt * TJ;

        // ---- compute alpha strip (unnormalized) in registers ----
        float pv[8];
#pragma unroll
        for (int r = 0; r < 8; r++) {
            float e = ssrc_r[r] + sd;
            e = fmaxf(e, NEG_SLOPE * e);          // leaky_relu
            float p = av[r] * __expf(e);          // adj is exactly 0.0/1.0
            lsum[r] += p;
            pv[r] = p;
        }
        __syncwarp();                              // prior reads of pwme done
        float4 plo; plo.x = pv[0]; plo.y = pv[1]; plo.z = pv[2]; plo.w = pv[3];
        float4 phi; phi.x = pv[4]; phi.y = pv[5]; phi.z = pv[6]; phi.w = pv[7];
        *(float4*)(pwme + lane * 8)     = plo;
        *(float4*)(pwme + lane * 8 + 4) = phi;
        __syncwarp();

        // ---- prefetch next tile's adj/sdst (hidden under FFMA phase) ----
        if (jt + 1 < Nq / TJ) {
            const int j1 = j0 + TJ;
            sd = __ldg(&g_sdst[(size_t)(bN + j1 + lane) * 4 + head]);
#pragma unroll
            for (int r = 0; r < 8; r++)
                av[r] = __ldg(adjbase + (size_t)r * Nq + j1 + lane);
        }

        // ---- rank-32 update on 2 columns x 8 rows ----
        const float* hrow = g_h + (size_t)(bN + j0) * DOUTq + c0;
#pragma unroll 4
        for (int jj = 0; jj < TJ; jj++) {
            float2 hv = __ldg((const float2*)(hrow + (size_t)jj * DOUTq));
            unsigned long long h0 = pack2(hv.x, hv.x);
            unsigned long long h1 = pack2(hv.y, hv.y);
            const uint4* pp = (const uint4*)(pwme + jj * 8);
            uint4 q0 = pp[0], q1 = pp[1];
            unsigned long long p01 = pack2(__uint_as_float(q0.x), __uint_as_float(q0.y));
            unsigned long long p23 = pack2(__uint_as_float(q0.z), __uint_as_float(q0.w));
            unsigned long long p45 = pack2(__uint_as_float(q1.x), __uint_as_float(q1.y));
            unsigned long long p67 = pack2(__uint_as_float(q1.z), __uint_as_float(q1.w));
            ffma2(accA[0], p01, h0); ffma2(accA[1], p23, h0);
            ffma2(accA[2], p45, h0); ffma2(accA[3], p67, h0);
            ffma2(accB[0], p01, h1); ffma2(accB[1], p23, h1);
            ffma2(accB[2], p45, h1); ffma2(accB[3], p67, h1);
        }
    }

    // ---- reduce denominators across lanes (butterfly: all lanes get total) ----
#pragma unroll
    for (int off = 16; off > 0; off >>= 1)
#pragma unroll
        for (int r = 0; r < 8; r++)
            lsum[r] += __shfl_xor_sync(0xFFFFFFFFu, lsum[r], off);

    float linv[8];
#pragma unroll
    for (int r = 0; r < 8; r++) linv[r] = 1.0f / lsum[r];

    // ---- scale + store: accA[e]=(ti 2e,2e+1) col c0, accB same col c0+1 ----
#pragma unroll
    for (int e = 0; e < 4; e++) {
        float aLo, aHi, bLo, bHi;
        unpack2(accA[e], aLo, aHi);
        unpack2(accB[e], bLo, bHi);
        const int r0 = 2 * e, r1 = 2 * e + 1;
        float2 o0; o0.x = aLo * linv[r0]; o0.y = bLo * linv[r0];
        float2 o1; o1.x = aHi * linv[r1]; o1.y = bHi * linv[r1];
        *(float2*)&out[(size_t)(rowb + tib + r0) * DOUTq + c0] = o0;
        *(float2*)&out[(size_t)(rowb + tib + r1) * DOUTq + c0] = o1;
    }
}

// =====================================================================
extern "C" void kernel_launch(void* const* d_in, const int* in_sizes, int n_in,
                              void* d_out, int out_size) {
    const float* x     = (const float*)d_in[0];   // [B,N,DIN]
    const float* adj   = (const float*)d_in[1];   // [B,N,N]
    const float* W     = (const float*)d_in[2];   // [DOUT,DIN]
    const float* a_src = (const float*)d_in[3];   // [H,HD]
    const float* a_dst = (const float*)d_in[4];   // [H,HD]
    float* out = (float*)d_out;                   // [B,N,DOUT]

    gemm_xWT_kernel<<<dim3((Bq * Nq) / 128, DOUTq / 64), 256>>>(x, W);
    score_kernel<<<(Bq * Nq * Hq) / 8, 256>>>(a_src, a_dst);
    agg_kernel<<<dim3(Nq / TI, Bq), 256>>>(adj, out);
}

// round 5
// speedup vs baseline: 1.6766x; 1.1423x over previous
#include <cuda_runtime.h>
#include <cstdint>

#define Bq    4
#define Nq    2048
#define DINq  256
#define DOUTq 256
#define Hq    4
#define HDq   64
#define NEG_SLOPE 0.2f

// ---------------- scratch (no allocation allowed) ----------------
__device__ float g_h[Bq * Nq * DOUTq];       // 8 MB: h = x @ W^T
__device__ float g_ssrc[Bq * Nq * Hq];
__device__ float g_sdst[Bq * Nq * Hq];

// ---------------- packed f32x2 helpers ----------------
__device__ __forceinline__ void ffma2(unsigned long long& acc,
                                      unsigned long long p,
                                      unsigned long long h) {
    asm("fma.rn.f32x2 %0, %1, %2, %0;" : "+l"(acc) : "l"(p), "l"(h));
}
__device__ __forceinline__ unsigned long long pack2(float lo, float hi) {
    unsigned long long r;
    asm("mov.b64 %0, {%1, %2};" : "=l"(r) : "f"(lo), "f"(hi));
    return r;
}
__device__ __forceinline__ void unpack2(unsigned long long v, float& lo, float& hi) {
    asm("mov.b64 {%0, %1}, %2;" : "=f"(lo), "=f"(hi) : "l"(v));
}

// =====================================================================
// Kernel 1: h = x @ W^T.  128x64 tile, 256 threads, 8x4 micro-tile with
// packed f32x2 accumulators.
// =====================================================================
__global__ __launch_bounds__(256) void gemm_xWT_kernel(const float* __restrict__ x,
                                                       const float* __restrict__ W) {
    __shared__ float as[16][132];
    __shared__ float bs[16][68];

    const int tid = threadIdx.x;
    const int tx = tid & 15;
    const int ty = tid >> 4;
    const int row0 = blockIdx.x * 128;
    const int col0 = blockIdx.y * 64;

    unsigned long long acc2[4][4];
#pragma unroll
    for (int i = 0; i < 4; i++)
#pragma unroll
        for (int j = 0; j < 4; j++) acc2[i][j] = 0ull;

    const int arow = tid >> 1;
    const int aq   = (tid & 1) * 8;
    const int brow = tid >> 2;
    const int bq   = (tid & 3) * 4;
    const float* xp = x + (size_t)(row0 + arow) * DINq + aq;
    const float* wp = W + (size_t)(col0 + brow) * DINq + bq;

    for (int kc = 0; kc < DINq; kc += 16) {
        float4 v0 = *(const float4*)(xp + kc);
        float4 v1 = *(const float4*)(xp + kc + 4);
        float4 wv = *(const float4*)(wp + kc);
        as[aq + 0][arow] = v0.x; as[aq + 1][arow] = v0.y;
        as[aq + 2][arow] = v0.z; as[aq + 3][arow] = v0.w;
        as[aq + 4][arow] = v1.x; as[aq + 5][arow] = v1.y;
        as[aq + 6][arow] = v1.z; as[aq + 7][arow] = v1.w;
        bs[bq + 0][brow] = wv.x; bs[bq + 1][brow] = wv.y;
        bs[bq + 2][brow] = wv.z; bs[bq + 3][brow] = wv.w;
        __syncthreads();

#pragma unroll
        for (int k = 0; k < 16; k++) {
            float a8[8], b4[4];
            *(float4*)a8       = *(const float4*)&as[k][ty * 8];
            *(float4*)(a8 + 4) = *(const float4*)&as[k][ty * 8 + 4];
            *(float4*)b4       = *(const float4*)&bs[k][tx * 4];
            unsigned long long bp[4];
#pragma unroll
            for (int j = 0; j < 4; j++) bp[j] = pack2(b4[j], b4[j]);
#pragma unroll
            for (int i = 0; i < 4; i++) {
                unsigned long long ap = pack2(a8[2 * i], a8[2 * i + 1]);
#pragma unroll
                for (int j = 0; j < 4; j++) ffma2(acc2[i][j], ap, bp[j]);
            }
        }
        __syncthreads();
    }

#pragma unroll
    for (int i = 0; i < 4; i++) {
        float lo[4], hi[4];
#pragma unroll
        for (int j = 0; j < 4; j++) unpack2(acc2[i][j], lo[j], hi[j]);
        float4 o0; o0.x = lo[0]; o0.y = lo[1]; o0.z = lo[2]; o0.w = lo[3];
        float4 o1; o1.x = hi[0]; o1.y = hi[1]; o1.z = hi[2]; o1.w = hi[3];
        const int r = row0 + ty * 8 + 2 * i;
        *(float4*)&g_h[(size_t)(r + 0) * DOUTq + col0 + tx * 4] = o0;
        *(float4*)&g_h[(size_t)(r + 1) * DOUTq + col0 + tx * 4] = o1;
    }
}

// =====================================================================
// Kernel 2: per-(row,head) scores via warp dot products
// =====================================================================
__global__ __launch_bounds__(256) void score_kernel(const float* __restrict__ a_src,
                                                    const float* __restrict__ a_dst) {
    const int task = blockIdx.x * 8 + (threadIdx.x >> 5);   // row*4 + head
    const int ln = threadIdx.x & 31;
    const int row = task >> 2;
    const int head = task & 3;

    const float* hp = g_h + (size_t)row * DOUTq + head * HDq;
    float v0 = hp[ln], v1 = hp[ln + 32];
    float s1 = v0 * a_src[head * HDq + ln] + v1 * a_src[head * HDq + ln + 32];
    float s2 = v0 * a_dst[head * HDq + ln] + v1 * a_dst[head * HDq + ln + 32];
#pragma unroll
    for (int off = 16; off > 0; off >>= 1) {
        s1 += __shfl_xor_sync(0xFFFFFFFFu, s1, off);
        s2 += __shfl_xor_sync(0xFFFFFFFFu, s2, off);
    }
    if (ln == 0) {
        g_ssrc[task] = s1;
        g_sdst[task] = s2;
    }
}

// =====================================================================
// Kernel 3: fused aggregation + inline softmax denominator.
// Warp-autonomous (no __syncthreads in main loop). Thread owns 2 cols,
// 8 i-rows. h loads run through an explicit 8-deep double-buffered
// register pipeline so ~8 LDG.64 are always in flight (L2-latency hiding).
// =====================================================================
#define TI 16
#define TJ 32

__global__ __launch_bounds__(256, 3) void agg_kernel(const float* __restrict__ adj,
                                                     float* __restrict__ out) {
    __shared__ __align__(16) float pw[8][TJ * 8];   // per-warp alpha [jj][ti8], 8 KB

    const int t = threadIdx.x;
    const int w = t >> 5;
    const int lane = t & 31;
    const int head = w & 3;
    const int tib = (w >> 2) * 8;       // 0 or 8
    const int g = t & 127;
    const int c0 = 2 * g;               // this thread's 2 output cols
    const int b = blockIdx.y;
    const int i0 = blockIdx.x * TI;
    const int rowb = b * Nq + i0;
    const int bN = b * Nq;

    float* pwme = &pw[w][0];

    float ssrc_r[8];
#pragma unroll
    for (int r = 0; r < 8; r++)
        ssrc_r[r] = g_ssrc[(size_t)(rowb + tib + r) * 4 + head];

    unsigned long long accA[4], accB[4];
#pragma unroll
    for (int q = 0; q < 4; q++) { accA[q] = 0ull; accB[q] = 0ull; }
    float lsum[8];
#pragma unroll
    for (int r = 0; r < 8; r++) lsum[r] = 0.f;

    const float* adjbase = adj + (size_t)(rowb + tib) * Nq;
    const float* hbase = g_h + (size_t)bN * DOUTq + c0;

    // prologue loads for jt = 0
    float av[8], sd;
    sd = __ldg(&g_sdst[(size_t)(bN + lane) * 4 + head]);
#pragma unroll
    for (int r = 0; r < 8; r++)
        av[r] = __ldg(adjbase + (size_t)r * Nq + lane);

    // h pipeline prologue: first 8 rows (j = 0..7)
    float2 hbuf[8];
#pragma unroll
    for (int u = 0; u < 8; u++)
        hbuf[u] = __ldg((const float2*)(hbase + (size_t)u * DOUTq));

    for (int jt = 0; jt < Nq / TJ; jt++) {
        const int j0 = jt * TJ;

        // ---- compute alpha strip (unnormalized) in registers ----
        float pv[8];
#pragma unroll
        for (int r = 0; r < 8; r++) {
            float e = ssrc_r[r] + sd;
            e = fmaxf(e, NEG_SLOPE * e);          // leaky_relu
            float p = av[r] * __expf(e);          // adj is exactly 0.0/1.0
            lsum[r] += p;
            pv[r] = p;
        }
        __syncwarp();                              // prior reads of pwme done
        float4 plo; plo.x = pv[0]; plo.y = pv[1]; plo.z = pv[2]; plo.w = pv[3];
        float4 phi; phi.x = pv[4]; phi.y = pv[5]; phi.z = pv[6]; phi.w = pv[7];
        *(float4*)(pwme + lane * 8)     = plo;
        *(float4*)(pwme + lane * 8 + 4) = phi;
        __syncwarp();

        // ---- prefetch next tile's adj/sdst (hidden under FFMA phase) ----
        if (jt + 1 < Nq / TJ) {
            const int j1 = j0 + TJ;
            sd = __ldg(&g_sdst[(size_t)(bN + j1 + lane) * 4 + head]);
#pragma unroll
            for (int r = 0; r < 8; r++)
                av[r] = __ldg(adjbase + (size_t)r * Nq + j1 + lane);
        }

        // ---- rank-32 update, 8-deep double-buffered h pipeline ----
#pragma unroll
        for (int jg = 0; jg < TJ; jg += 8) {
            float2 hcur[8];
#pragma unroll
            for (int u = 0; u < 8; u++) hcur[u] = hbuf[u];

            // issue next group's loads before consuming current group
            const int jn = j0 + jg + 8;            // next group start (global j)
            if (jn < Nq) {
#pragma unroll
                for (int u = 0; u < 8; u++)
                    hbuf[u] = __ldg((const float2*)(hbase + (size_t)(jn + u) * DOUTq));
            }

#pragma unroll
            for (int u = 0; u < 8; u++) {
                const int jj = jg + u;
                unsigned long long h0 = pack2(hcur[u].x, hcur[u].x);
                unsigned long long h1 = pack2(hcur[u].y, hcur[u].y);
                const uint4* pp = (const uint4*)(pwme + jj * 8);
                uint4 q0 = pp[0], q1 = pp[1];
                unsigned long long p01 = pack2(__uint_as_float(q0.x), __uint_as_float(q0.y));
                unsigned long long p23 = pack2(__uint_as_float(q0.z), __uint_as_float(q0.w));
                unsigned long long p45 = pack2(__uint_as_float(q1.x), __uint_as_float(q1.y));
                unsigned long long p67 = pack2(__uint_as_float(q1.z), __uint_as_float(q1.w));
                ffma2(accA[0], p01, h0); ffma2(accA[1], p23, h0);
                ffma2(accA[2], p45, h0); ffma2(accA[3], p67, h0);
                ffma2(accB[0], p01, h1); ffma2(accB[1], p23, h1);
                ffma2(accB[2], p45, h1); ffma2(accB[3], p67, h1);
            }
        }
    }

    // ---- reduce denominators across lanes ----
#pragma unroll
    for (int off = 16; off > 0; off >>= 1)
#pragma unroll
        for (int r = 0; r < 8; r++)
            lsum[r] += __shfl_xor_sync(0xFFFFFFFFu, lsum[r], off);

    float linv[8];
#pragma unroll
    for (int r = 0; r < 8; r++) linv[r] = 1.0f / lsum[r];

    // ---- scale + store ----
#pragma unroll
    for (int e = 0; e < 4; e++) {
        float aLo, aHi, bLo, bHi;
        unpack2(accA[e], aLo, aHi);
        unpack2(accB[e], bLo, bHi);
        const int r0 = 2 * e, r1 = 2 * e + 1;
        float2 o0; o0.x = aLo * linv[r0]; o0.y = bLo * linv[r0];
        float2 o1; o1.x = aHi * linv[r1]; o1.y = bHi * linv[r1];
        *(float2*)&out[(size_t)(rowb + tib + r0) * DOUTq + c0] = o0;
        *(float2*)&out[(size_t)(rowb + tib + r1) * DOUTq + c0] = o1;
    }
}

// =====================================================================
extern "C" void kernel_launch(void* const* d_in, const int* in_sizes, int n_in,
                              void* d_out, int out_size) {
    const float* x     = (const float*)d_in[0];   // [B,N,DIN]
    const float* adj   = (const float*)d_in[1];   // [B,N,N]
    const float* W     = (const float*)d_in[2];   // [DOUT,DIN]
    const float* a_src = (const float*)d_in[3];   // [H,HD]
    const float* a_dst = (const float*)d_in[4];   // [H,HD]
    float* out = (float*)d_out;                   // [B,N,DOUT]

    gemm_xWT_kernel<<<dim3((Bq * Nq) / 128, DOUTq / 64), 256>>>(x, W);
    score_kernel<<<(Bq * Nq * Hq) / 8, 256>>>(a_src, a_dst);
    agg_kernel<<<dim3(Nq / TI, Bq), 256>>>(adj, out);
}

// round 6
// speedup vs baseline: 2.5573x; 1.5252x over previous
#include <cuda_runtime.h>
#include <cstdint>

#define Bq    4
#define Nq    2048
#define DINq  256
#define DOUTq 256
#define Hq    4
#define HDq   64
#define NEG_SLOPE 0.2f

// ---------------- scratch (no allocation allowed) ----------------
__device__ float g_h[Bq * Nq * DOUTq];       // 8 MB: h = x @ W^T
__device__ float g_ssrc[Bq * Nq * Hq];
__device__ float g_sdst[Bq * Nq * Hq];

// ---------------- packed f32x2 helpers (gemm) ----------------
__device__ __forceinline__ void ffma2(unsigned long long& acc,
                                      unsigned long long p,
                                      unsigned long long h) {
    asm("fma.rn.f32x2 %0, %1, %2, %0;" : "+l"(acc) : "l"(p), "l"(h));
}
__device__ __forceinline__ unsigned long long pack2(float lo, float hi) {
    unsigned long long r;
    asm("mov.b64 %0, {%1, %2};" : "=l"(r) : "f"(lo), "f"(hi));
    return r;
}
__device__ __forceinline__ void unpack2(unsigned long long v, float& lo, float& hi) {
    asm("mov.b64 {%0, %1}, %2;" : "=f"(lo), "=f"(hi) : "l"(v));
}

// ---------------- tf32 mma helpers ----------------
__device__ __forceinline__ uint32_t f2tf32(float f) {
    uint32_t r;
    asm("cvt.rna.tf32.f32 %0, %1;" : "=r"(r) : "f"(f));
    return r;
}
__device__ __forceinline__ void mma_tf32(float* d, const uint32_t* a, const uint32_t* b) {
    asm volatile(
        "mma.sync.aligned.m16n8k8.row.col.f32.tf32.tf32.f32 "
        "{%0,%1,%2,%3}, {%4,%5,%6,%7}, {%8,%9}, {%0,%1,%2,%3};"
        : "+f"(d[0]), "+f"(d[1]), "+f"(d[2]), "+f"(d[3])
        : "r"(a[0]), "r"(a[1]), "r"(a[2]), "r"(a[3]), "r"(b[0]), "r"(b[1]));
}

// =====================================================================
// Kernel 1: h = x @ W^T.  128x64 tile, 256 threads, 8x4 micro-tile.
// =====================================================================
__global__ __launch_bounds__(256) void gemm_xWT_kernel(const float* __restrict__ x,
                                                       const float* __restrict__ W) {
    __shared__ float as[16][132];
    __shared__ float bs[16][68];

    const int tid = threadIdx.x;
    const int tx = tid & 15;
    const int ty = tid >> 4;
    const int row0 = blockIdx.x * 128;
    const int col0 = blockIdx.y * 64;

    unsigned long long acc2[4][4];
#pragma unroll
    for (int i = 0; i < 4; i++)
#pragma unroll
        for (int j = 0; j < 4; j++) acc2[i][j] = 0ull;

    const int arow = tid >> 1;
    const int aq   = (tid & 1) * 8;
    const int brow = tid >> 2;
    const int bq   = (tid & 3) * 4;
    const float* xp = x + (size_t)(row0 + arow) * DINq + aq;
    const float* wp = W + (size_t)(col0 + brow) * DINq + bq;

    for (int kc = 0; kc < DINq; kc += 16) {
        float4 v0 = *(const float4*)(xp + kc);
        float4 v1 = *(const float4*)(xp + kc + 4);
        float4 wv = *(const float4*)(wp + kc);
        as[aq + 0][arow] = v0.x; as[aq + 1][arow] = v0.y;
        as[aq + 2][arow] = v0.z; as[aq + 3][arow] = v0.w;
        as[aq + 4][arow] = v1.x; as[aq + 5][arow] = v1.y;
        as[aq + 6][arow] = v1.z; as[aq + 7][arow] = v1.w;
        bs[bq + 0][brow] = wv.x; bs[bq + 1][brow] = wv.y;
        bs[bq + 2][brow] = wv.z; bs[bq + 3][brow] = wv.w;
        __syncthreads();

#pragma unroll
        for (int k = 0; k < 16; k++) {
            float a8[8], b4[4];
            *(float4*)a8       = *(const float4*)&as[k][ty * 8];
            *(float4*)(a8 + 4) = *(const float4*)&as[k][ty * 8 + 4];
            *(float4*)b4       = *(const float4*)&bs[k][tx * 4];
            unsigned long long bp[4];
#pragma unroll
            for (int j = 0; j < 4; j++) bp[j] = pack2(b4[j], b4[j]);
#pragma unroll
            for (int i = 0; i < 4; i++) {
                unsigned long long ap = pack2(a8[2 * i], a8[2 * i + 1]);
#pragma unroll
                for (int j = 0; j < 4; j++) ffma2(acc2[i][j], ap, bp[j]);
            }
        }
        __syncthreads();
    }

#pragma unroll
    for (int i = 0; i < 4; i++) {
        float lo[4], hi[4];
#pragma unroll
        for (int j = 0; j < 4; j++) unpack2(acc2[i][j], lo[j], hi[j]);
        float4 o0; o0.x = lo[0]; o0.y = lo[1]; o0.z = lo[2]; o0.w = lo[3];
        float4 o1; o1.x = hi[0]; o1.y = hi[1]; o1.z = hi[2]; o1.w = hi[3];
        const int r = row0 + ty * 8 + 2 * i;
        *(float4*)&g_h[(size_t)(r + 0) * DOUTq + col0 + tx * 4] = o0;
        *(float4*)&g_h[(size_t)(r + 1) * DOUTq + col0 + tx * 4] = o1;
    }
}

// =====================================================================
// Kernel 2: per-(row,head) scores via warp dot products
// =====================================================================
__global__ __launch_bounds__(256) void score_kernel(const float* __restrict__ a_src,
                                                    const float* __restrict__ a_dst) {
    const int task = blockIdx.x * 8 + (threadIdx.x >> 5);   // row*4 + head
    const int ln = threadIdx.x & 31;
    const int row = task >> 2;
    const int head = task & 3;

    const float* hp = g_h + (size_t)row * DOUTq + head * HDq;
    float v0 = hp[ln], v1 = hp[ln + 32];
    float s1 = v0 * a_src[head * HDq + ln] + v1 * a_src[head * HDq + ln + 32];
    float s2 = v0 * a_dst[head * HDq + ln] + v1 * a_dst[head * HDq + ln + 32];
#pragma unroll
    for (int off = 16; off > 0; off >>= 1) {
        s1 += __shfl_xor_sync(0xFFFFFFFFu, s1, off);
        s2 += __shfl_xor_sync(0xFFFFFFFFu, s2, off);
    }
    if (ln == 0) {
        g_ssrc[task] = s1;
        g_sdst[task] = s2;
    }
}

// =====================================================================
// Kernel 3: tensor-core aggregation (tf32 mma) + fused softmax denom.
// Block = 128 thr / 4 warps, i-tile = 32 rows, grid (N/32, B).
// Warp w computes head w:  D[32 x 64] = P_w[32 x 2048] @ h[:, w*64..].
// Per 32-j chunk:
//   P-phase: warp w computes P rows w*8..w*8+7 for ALL heads (coalesced
//            adj loads), tf32-rounds, stores to double-buffered smem.
//   __syncthreads (1/chunk; write buf c&1, read buf c&1; reuse safe).
//   mma-phase: B frags LDG'd from L2-resident h; A frags LDS'd.
//   Extra "ones" accumulator per m16 subtile: lsum[i] = sum_j P[i,j]
//   computed by the tensor core (col 0 of a 9th mma).
// Epilogue: out = D * (1/lsum) broadcast via shfl.
// =====================================================================
__global__ __launch_bounds__(128) void agg_mma_kernel(const float* __restrict__ adj,
                                                      float* __restrict__ out) {
    __shared__ uint32_t sP[2][Hq][32][36];   // tf32 alpha, double buffered (36.9 KB)
    __shared__ float sS[32][4];              // ssrc rows of this i-tile

    const int t = threadIdx.x;
    const int w = t >> 5;          // warp = head (mma phase), row-group (P phase)
    const int lane = t & 31;
    const int g = lane >> 2;       // groupID
    const int ct = lane & 3;       // thread-in-group
    const int b = blockIdx.y;
    const int i0 = blockIdx.x * 32;
    const int bN = b * Nq;

    if (t < 32)
        *(float4*)&sS[t][0] = *(const float4*)&g_ssrc[(size_t)(bN + i0 + t) * 4];
    __syncthreads();

    float d[2][8][4];              // [m16 sub][n8 tile][frag]
    float dones[2][4];
#pragma unroll
    for (int s = 0; s < 2; s++) {
#pragma unroll
        for (int nt = 0; nt < 8; nt++)
#pragma unroll
            for (int q = 0; q < 4; q++) d[s][nt][q] = 0.f;
#pragma unroll
        for (int q = 0; q < 4; q++) dones[s][q] = 0.f;
    }

    uint32_t bones[2];
    bones[0] = bones[1] = (g == 0) ? __float_as_uint(1.0f) : 0u;

    const float* hcolbase = g_h + (size_t)bN * DOUTq + w * HDq;

    for (int c = 0; c < Nq / 32; c++) {
        const int j0 = c * 32;
        const int buf = c & 1;

        // ---------- P-phase: rows w*8 .. w*8+7, all 4 heads ----------
        {
            float4 sd4 = __ldg((const float4*)&g_sdst[(size_t)(bN + j0 + lane) * 4]);
#pragma unroll
            for (int r = 0; r < 8; r++) {
                const int row = w * 8 + r;
                float av = __ldg(&adj[(size_t)(bN + i0 + row) * Nq + j0 + lane]);
                float4 ss = *(const float4*)&sS[row][0];
                float e0 = ss.x + sd4.x; e0 = fmaxf(e0, NEG_SLOPE * e0);
                float e1 = ss.y + sd4.y; e1 = fmaxf(e1, NEG_SLOPE * e1);
                float e2 = ss.z + sd4.z; e2 = fmaxf(e2, NEG_SLOPE * e2);
                float e3 = ss.w + sd4.w; e3 = fmaxf(e3, NEG_SLOPE * e3);
                sP[buf][0][row][lane] = f2tf32(av * __expf(e0));
                sP[buf][1][row][lane] = f2tf32(av * __expf(e1));
                sP[buf][2][row][lane] = f2tf32(av * __expf(e2));
                sP[buf][3][row][lane] = f2tf32(av * __expf(e3));
            }
        }
        __syncthreads();

        // ---------- mma-phase: head w ----------
        const float* hc = hcolbase + (size_t)j0 * DOUTq;
#pragma unroll
        for (int kk = 0; kk < 4; kk++) {
            // B fragments: 8 n-tiles x 2 regs, batched LDG then cvt
            float braw[8][2];
            const float* hb = hc + (size_t)(kk * 8 + ct) * DOUTq + g;
#pragma unroll
            for (int nt = 0; nt < 8; nt++) {
                braw[nt][0] = __ldg(hb + nt * 8);
                braw[nt][1] = __ldg(hb + 4 * DOUTq + nt * 8);
            }
            uint32_t bf[8][2];
#pragma unroll
            for (int nt = 0; nt < 8; nt++) {
                bf[nt][0] = f2tf32(braw[nt][0]);
                bf[nt][1] = f2tf32(braw[nt][1]);
            }
#pragma unroll
            for (int s = 0; s < 2; s++) {
                const int ar = s * 16 + g;
                const int acl = kk * 8 + ct;
                uint32_t af[4];
                af[0] = sP[buf][w][ar][acl];
                af[1] = sP[buf][w][ar + 8][acl];
                af[2] = sP[buf][w][ar][acl + 4];
                af[3] = sP[buf][w][ar + 8][acl + 4];
#pragma unroll
                for (int nt = 0; nt < 8; nt++) mma_tf32(d[s][nt], af, bf[nt]);
                mma_tf32(dones[s], af, bones);
            }
        }
    }

    // ---------- epilogue: normalize and store ----------
#pragma unroll
    for (int s = 0; s < 2; s++) {
        // lsum[row g] sits in dones[s][0] of lane 4g; lsum[g+8] in dones[s][2]
        float lA = __shfl_sync(0xFFFFFFFFu, dones[s][0], lane & ~3);
        float lB = __shfl_sync(0xFFFFFFFFu, dones[s][2], lane & ~3);
        float liA = 1.0f / lA;
        float liB = 1.0f / lB;
        const int rowA = i0 + s * 16 + g;
        const int rowB = rowA + 8;
        const int col = w * HDq + 2 * ct;
#pragma unroll
        for (int nt = 0; nt < 8; nt++) {
            float2 oA; oA.x = d[s][nt][0] * liA; oA.y = d[s][nt][1] * liA;
            float2 oB; oB.x = d[s][nt][2] * liB; oB.y = d[s][nt][3] * liB;
            *(float2*)&out[(size_t)(bN + rowA) * DOUTq + col + nt * 8] = oA;
            *(float2*)&out[(size_t)(bN + rowB) * DOUTq + col + nt * 8] = oB;
        }
    }
}

// =====================================================================
extern "C" void kernel_launch(void* const* d_in, const int* in_sizes, int n_in,
                              void* d_out, int out_size) {
    const float* x     = (const float*)d_in[0];   // [B,N,DIN]
    const float* adj   = (const float*)d_in[1];   // [B,N,N]
    const float* W     = (const float*)d_in[2];   // [DOUT,DIN]
    const float* a_src = (const float*)d_in[3];   // [H,HD]
    const float* a_dst = (const float*)d_in[4];   // [H,HD]
    float* out = (float*)d_out;                   // [B,N,DOUT]

    gemm_xWT_kernel<<<dim3((Bq * Nq) / 128, DOUTq / 64), 256>>>(x, W);
    score_kernel<<<(Bq * Nq * Hq) / 8, 256>>>(a_src, a_dst);
    agg_mma_kernel<<<dim3(Nq / 32, Bq), 128>>>(adj, out);
}

// round 7
// speedup vs baseline: 3.4016x; 1.3302x over previous
#include <cuda_runtime.h>
#include <cstdint>

#define Bq    4
#define Nq    2048
#define DINq  256
#define DOUTq 256
#define Hq    4
#define HDq   64
#define NEG_SLOPE 0.2f

// ---------------- scratch (no allocation allowed) ----------------
__device__ float g_h[Bq * Nq * DOUTq];       // 8 MB: h = x @ W^T
__device__ float g_ssrc[Bq * Nq * Hq];
__device__ float g_sdst[Bq * Nq * Hq];

// ---------------- packed f32x2 helpers (gemm) ----------------
__device__ __forceinline__ void ffma2(unsigned long long& acc,
                                      unsigned long long p,
                                      unsigned long long h) {
    asm("fma.rn.f32x2 %0, %1, %2, %0;" : "+l"(acc) : "l"(p), "l"(h));
}
__device__ __forceinline__ unsigned long long pack2(float lo, float hi) {
    unsigned long long r;
    asm("mov.b64 %0, {%1, %2};" : "=l"(r) : "f"(lo), "f"(hi));
    return r;
}
__device__ __forceinline__ void unpack2(unsigned long long v, float& lo, float& hi) {
    asm("mov.b64 {%0, %1}, %2;" : "=f"(lo), "=f"(hi) : "l"(v));
}

// ---------------- tf32 mma helpers ----------------
__device__ __forceinline__ uint32_t f2tf32(float f) {
    uint32_t r;
    asm("cvt.rna.tf32.f32 %0, %1;" : "=r"(r) : "f"(f));
    return r;
}
__device__ __forceinline__ void mma_tf32(float* d, const uint32_t* a, const uint32_t* b) {
    asm volatile(
        "mma.sync.aligned.m16n8k8.row.col.f32.tf32.tf32.f32 "
        "{%0,%1,%2,%3}, {%4,%5,%6,%7}, {%8,%9}, {%0,%1,%2,%3};"
        : "+f"(d[0]), "+f"(d[1]), "+f"(d[2]), "+f"(d[3])
        : "r"(a[0]), "r"(a[1]), "r"(a[2]), "r"(a[3]), "r"(b[0]), "r"(b[1]));
}

// =====================================================================
// Kernel 1: h = x @ W^T.  128x64 tile, 256 threads, 8x4 micro-tile.
// =====================================================================
__global__ __launch_bounds__(256) void gemm_xWT_kernel(const float* __restrict__ x,
                                                       const float* __restrict__ W) {
    __shared__ float as[16][132];
    __shared__ float bs[16][68];

    const int tid = threadIdx.x;
    const int tx = tid & 15;
    const int ty = tid >> 4;
    const int row0 = blockIdx.x * 128;
    const int col0 = blockIdx.y * 64;

    unsigned long long acc2[4][4];
#pragma unroll
    for (int i = 0; i < 4; i++)
#pragma unroll
        for (int j = 0; j < 4; j++) acc2[i][j] = 0ull;

    const int arow = tid >> 1;
    const int aq   = (tid & 1) * 8;
    const int brow = tid >> 2;
    const int bq   = (tid & 3) * 4;
    const float* xp = x + (size_t)(row0 + arow) * DINq + aq;
    const float* wp = W + (size_t)(col0 + brow) * DINq + bq;

    for (int kc = 0; kc < DINq; kc += 16) {
        float4 v0 = *(const float4*)(xp + kc);
        float4 v1 = *(const float4*)(xp + kc + 4);
        float4 wv = *(const float4*)(wp + kc);
        as[aq + 0][arow] = v0.x; as[aq + 1][arow] = v0.y;
        as[aq + 2][arow] = v0.z; as[aq + 3][arow] = v0.w;
        as[aq + 4][arow] = v1.x; as[aq + 5][arow] = v1.y;
        as[aq + 6][arow] = v1.z; as[aq + 7][arow] = v1.w;
        bs[bq + 0][brow] = wv.x; bs[bq + 1][brow] = wv.y;
        bs[bq + 2][brow] = wv.z; bs[bq + 3][brow] = wv.w;
        __syncthreads();

#pragma unroll
        for (int k = 0; k < 16; k++) {
            float a8[8], b4[4];
            *(float4*)a8       = *(const float4*)&as[k][ty * 8];
            *(float4*)(a8 + 4) = *(const float4*)&as[k][ty * 8 + 4];
            *(float4*)b4       = *(const float4*)&bs[k][tx * 4];
            unsigned long long bp[4];
#pragma unroll
            for (int j = 0; j < 4; j++) bp[j] = pack2(b4[j], b4[j]);
#pragma unroll
            for (int i = 0; i < 4; i++) {
                unsigned long long ap = pack2(a8[2 * i], a8[2 * i + 1]);
#pragma unroll
                for (int j = 0; j < 4; j++) ffma2(acc2[i][j], ap, bp[j]);
            }
        }
        __syncthreads();
    }

#pragma unroll
    for (int i = 0; i < 4; i++) {
        float lo[4], hi[4];
#pragma unroll
        for (int j = 0; j < 4; j++) unpack2(acc2[i][j], lo[j], hi[j]);
        float4 o0; o0.x = lo[0]; o0.y = lo[1]; o0.z = lo[2]; o0.w = lo[3];
        float4 o1; o1.x = hi[0]; o1.y = hi[1]; o1.z = hi[2]; o1.w = hi[3];
        const int r = row0 + ty * 8 + 2 * i;
        *(float4*)&g_h[(size_t)(r + 0) * DOUTq + col0 + tx * 4] = o0;
        *(float4*)&g_h[(size_t)(r + 1) * DOUTq + col0 + tx * 4] = o1;
    }
}

// =====================================================================
// Kernel 2: per-(row,head) scores via warp dot products
// =====================================================================
__global__ __launch_bounds__(256) void score_kernel(const float* __restrict__ a_src,
                                                    const float* __restrict__ a_dst) {
    const int task = blockIdx.x * 8 + (threadIdx.x >> 5);   // row*4 + head
    const int ln = threadIdx.x & 31;
    const int row = task >> 2;
    const int head = task & 3;

    const float* hp = g_h + (size_t)row * DOUTq + head * HDq;
    float v0 = hp[ln], v1 = hp[ln + 32];
    float s1 = v0 * a_src[head * HDq + ln] + v1 * a_src[head * HDq + ln + 32];
    float s2 = v0 * a_dst[head * HDq + ln] + v1 * a_dst[head * HDq + ln + 32];
#pragma unroll
    for (int off = 16; off > 0; off >>= 1) {
        s1 += __shfl_xor_sync(0xFFFFFFFFu, s1, off);
        s2 += __shfl_xor_sync(0xFFFFFFFFu, s2, off);
    }
    if (ln == 0) {
        g_ssrc[task] = s1;
        g_sdst[task] = s2;
    }
}

// =====================================================================
// Kernel 3: tensor-core aggregation (tf32 mma) + fused softmax denom.
// Block = 256 thr / 8 warps, i-tile = 32 rows, grid (N/32, B).
// Warp w = (head = w&3, nhalf = w>>2): m=32 rows, n=32 cols of its head.
// Per 32-j chunk:
//   P-phase: warp w computes P rows w*4..w*4+3 for ALL heads, tf32-rounds,
//            stores to double-buffered smem. Next chunk's adj/sdst are
//            prefetched into registers before the barrier.
//   mma-phase: B frags LDG'd from L2-resident h; A frags LDS'd.
//   Ones-mma per m16 subtile gives lsum (softmax denominator) in-core.
// =====================================================================
__global__ __launch_bounds__(256) void agg_mma_kernel(const float* __restrict__ adj,
                                                      float* __restrict__ out) {
    __shared__ uint32_t sP[2][Hq][32][36];   // tf32 alpha, double buffered (36.9 KB)
    __shared__ float sS[32][4];              // ssrc rows of this i-tile

    const int t = threadIdx.x;
    const int w = t >> 5;
    const int lane = t & 31;
    const int head = w & 3;
    const int nh = w >> 2;         // n-half: 0 or 1
    const int g = lane >> 2;       // groupID
    const int ct = lane & 3;       // thread-in-group
    const int b = blockIdx.y;
    const int i0 = blockIdx.x * 32;
    const int bN = b * Nq;

    if (t < 32)
        *(float4*)&sS[t][0] = *(const float4*)&g_ssrc[(size_t)(bN + i0 + t) * 4];
    __syncthreads();

    float d[2][4][4];              // [m16 sub][n8 tile][frag]
    float dones[2][4];
#pragma unroll
    for (int s = 0; s < 2; s++) {
#pragma unroll
        for (int nt = 0; nt < 4; nt++)
#pragma unroll
            for (int q = 0; q < 4; q++) d[s][nt][q] = 0.f;
#pragma unroll
        for (int q = 0; q < 4; q++) dones[s][q] = 0.f;
    }

    uint32_t bones[2];
    bones[0] = bones[1] = (g == 0) ? __float_as_uint(1.0f) : 0u;

    const float* hcolbase = g_h + (size_t)bN * DOUTq + head * HDq + nh * 32;
    const float* adjbase = adj + (size_t)(bN + i0 + w * 4) * Nq;

    // prologue: chunk 0 adj/sdst
    float av[4];
    float4 sd4;
    sd4 = __ldg((const float4*)&g_sdst[(size_t)(bN + lane) * 4]);
#pragma unroll
    for (int r = 0; r < 4; r++)
        av[r] = __ldg(adjbase + (size_t)r * Nq + lane);

    for (int c = 0; c < Nq / 32; c++) {
        const int j0 = c * 32;
        const int buf = c & 1;

        // ---------- P-phase: rows w*4 .. w*4+3, all 4 heads ----------
#pragma unroll
        for (int r = 0; r < 4; r++) {
            const int row = w * 4 + r;
            float avr = av[r];
            float4 ss = *(const float4*)&sS[row][0];
            float e0 = ss.x + sd4.x; e0 = fmaxf(e0, NEG_SLOPE * e0);
            float e1 = ss.y + sd4.y; e1 = fmaxf(e1, NEG_SLOPE * e1);
            float e2 = ss.z + sd4.z; e2 = fmaxf(e2, NEG_SLOPE * e2);
            float e3 = ss.w + sd4.w; e3 = fmaxf(e3, NEG_SLOPE * e3);
            sP[buf][0][row][lane] = f2tf32(avr * __expf(e0));
            sP[buf][1][row][lane] = f2tf32(avr * __expf(e1));
            sP[buf][2][row][lane] = f2tf32(avr * __expf(e2));
            sP[buf][3][row][lane] = f2tf32(avr * __expf(e3));
        }

        // ---------- prefetch next chunk's adj/sdst (rides under barrier+mma) ----
        if (c + 1 < Nq / 32) {
            const int j1 = j0 + 32;
            sd4 = __ldg((const float4*)&g_sdst[(size_t)(bN + j1 + lane) * 4]);
#pragma unroll
            for (int r = 0; r < 4; r++)
                av[r] = __ldg(adjbase + (size_t)r * Nq + j1 + lane);
        }
        __syncthreads();

        // ---------- mma-phase: head, n-half ----------
        const float* hc = hcolbase + (size_t)j0 * DOUTq;
#pragma unroll
        for (int kk = 0; kk < 4; kk++) {
            float braw[4][2];
            const float* hb = hc + (size_t)(kk * 8 + ct) * DOUTq + g;
#pragma unroll
            for (int nt = 0; nt < 4; nt++) {
                braw[nt][0] = __ldg(hb + nt * 8);
                braw[nt][1] = __ldg(hb + 4 * DOUTq + nt * 8);
            }
            uint32_t bf[4][2];
#pragma unroll
            for (int nt = 0; nt < 4; nt++) {
                bf[nt][0] = f2tf32(braw[nt][0]);
                bf[nt][1] = f2tf32(braw[nt][1]);
            }
#pragma unroll
            for (int s = 0; s < 2; s++) {
                const int ar = s * 16 + g;
                const int acl = kk * 8 + ct;
                uint32_t af[4];
                af[0] = sP[buf][head][ar][acl];
                af[1] = sP[buf][head][ar + 8][acl];
                af[2] = sP[buf][head][ar][acl + 4];
                af[3] = sP[buf][head][ar + 8][acl + 4];
#pragma unroll
                for (int nt = 0; nt < 4; nt++) mma_tf32(d[s][nt], af, bf[nt]);
                mma_tf32(dones[s], af, bones);
            }
        }
    }

    // ---------- epilogue: normalize and store ----------
#pragma unroll
    for (int s = 0; s < 2; s++) {
        float lA = __shfl_sync(0xFFFFFFFFu, dones[s][0], lane & ~3);
        float lB = __shfl_sync(0xFFFFFFFFu, dones[s][2], lane & ~3);
        float liA = 1.0f / lA;
        float liB = 1.0f / lB;
        const int rowA = i0 + s * 16 + g;
        const int rowB = rowA + 8;
        const int col = head * HDq + nh * 32 + 2 * ct;
#pragma unroll
        for (int nt = 0; nt < 4; nt++) {
            float2 oA; oA.x = d[s][nt][0] * liA; oA.y = d[s][nt][1] * liA;
            float2 oB; oB.x = d[s][nt][2] * liB; oB.y = d[s][nt][3] * liB;
            *(float2*)&out[(size_t)(bN + rowA) * DOUTq + col + nt * 8] = oA;
            *(float2*)&out[(size_t)(bN + rowB) * DOUTq + col + nt * 8] = oB;
        }
    }
}

// =====================================================================
extern "C" void kernel_launch(void* const* d_in, const int* in_sizes, int n_in,
                              void* d_out, int out_size) {
    const float* x     = (const float*)d_in[0];   // [B,N,DIN]
    const float* adj   = (const float*)d_in[1];   // [B,N,N]
    const float* W     = (const float*)d_in[2];   // [DOUT,DIN]
    const float* a_src = (const float*)d_in[3];   // [H,HD]
    const float* a_dst = (const float*)d_in[4];   // [H,HD]
    float* out = (float*)d_out;                   // [B,N,DOUT]

    gemm_xWT_kernel<<<dim3((Bq * Nq) / 128, DOUTq / 64), 256>>>(x, W);
    score_kernel<<<(Bq * Nq * Hq) / 8, 256>>>(a_src, a_dst);
    agg_mma_kernel<<<dim3(Nq / 32, Bq), 256>>>(adj, out);
}

// round 10
// speedup vs baseline: 3.6619x; 1.0765x over previous
#include <cuda_runtime.h>
#include <cstdint>

#define Bq    4
#define Nq    2048
#define DINq  256
#define DOUTq 256
#define Hq    4
#define HDq   64
#define NEG_SLOPE 0.2f

// ---------------- scratch (no allocation allowed) ----------------
__device__ float g_h[Bq * Nq * DOUTq];       // 8 MB: h = x @ W^T
__device__ float g_ssrc[Bq * Nq * Hq];
__device__ float g_sdst[Bq * Nq * Hq];

// ---------------- packed f32x2 helpers (gemm) ----------------
__device__ __forceinline__ void ffma2(unsigned long long& acc,
                                      unsigned long long p,
                                      unsigned long long h) {
    asm("fma.rn.f32x2 %0, %1, %2, %0;" : "+l"(acc) : "l"(p), "l"(h));
}
__device__ __forceinline__ unsigned long long pack2(float lo, float hi) {
    unsigned long long r;
    asm("mov.b64 %0, {%1, %2};" : "=l"(r) : "f"(lo), "f"(hi));
    return r;
}
__device__ __forceinline__ void unpack2(unsigned long long v, float& lo, float& hi) {
    asm("mov.b64 {%0, %1}, %2;" : "=f"(lo), "=f"(hi) : "l"(v));
}

// ---------------- tf32 mma helpers ----------------
__device__ __forceinline__ uint32_t f2tf32(float f) {
    uint32_t r;
    asm("cvt.rna.tf32.f32 %0, %1;" : "=r"(r) : "f"(f));
    return r;
}
__device__ __forceinline__ void mma_tf32(float* d, const uint32_t* a, const uint32_t* b) {
    asm volatile(
        "mma.sync.aligned.m16n8k8.row.col.f32.tf32.tf32.f32 "
        "{%0,%1,%2,%3}, {%4,%5,%6,%7}, {%8,%9}, {%0,%1,%2,%3};"
        : "+f"(d[0]), "+f"(d[1]), "+f"(d[2]), "+f"(d[3])
        : "r"(a[0]), "r"(a[1]), "r"(a[2]), "r"(a[3]), "r"(b[0]), "r"(b[1]));
}

// =====================================================================
// Kernel 1: h = x @ W^T.  128x64 tile, 256 threads, 8x4 micro-tile.
// =====================================================================
__global__ __launch_bounds__(256) void gemm_xWT_kernel(const float* __restrict__ x,
                                                       const float* __restrict__ W) {
    __shared__ float as[16][132];
    __shared__ float bs[16][68];

    const int tid = threadIdx.x;
    const int tx = tid & 15;
    const int ty = tid >> 4;
    const int row0 = blockIdx.x * 128;
    const int col0 = blockIdx.y * 64;

    unsigned long long acc2[4][4];
#pragma unroll
    for (int i = 0; i < 4; i++)
#pragma unroll
        for (int j = 0; j < 4; j++) acc2[i][j] = 0ull;

    const int arow = tid >> 1;
    const int aq   = (tid & 1) * 8;
    const int brow = tid >> 2;
    const int bq   = (tid & 3) * 4;
    const float* xp = x + (size_t)(row0 + arow) * DINq + aq;
    const float* wp = W + (size_t)(col0 + brow) * DINq + bq;

    for (int kc = 0; kc < DINq; kc += 16) {
        float4 v0 = *(const float4*)(xp + kc);
        float4 v1 = *(const float4*)(xp + kc + 4);
        float4 wv = *(const float4*)(wp + kc);
        as[aq + 0][arow] = v0.x; as[aq + 1][arow] = v0.y;
        as[aq + 2][arow] = v0.z; as[aq + 3][arow] = v0.w;
        as[aq + 4][arow] = v1.x; as[aq + 5][arow] = v1.y;
        as[aq + 6][arow] = v1.z; as[aq + 7][arow] = v1.w;
        bs[bq + 0][brow] = wv.x; bs[bq + 1][brow] = wv.y;
        bs[bq + 2][brow] = wv.z; bs[bq + 3][brow] = wv.w;
        __syncthreads();

#pragma unroll
        for (int k = 0; k < 16; k++) {
            float a8[8], b4[4];
            *(float4*)a8       = *(const float4*)&as[k][ty * 8];
            *(float4*)(a8 + 4) = *(const float4*)&as[k][ty * 8 + 4];
            *(float4*)b4       = *(const float4*)&bs[k][tx * 4];
            unsigned long long bp[4];
#pragma unroll
            for (int j = 0; j < 4; j++) bp[j] = pack2(b4[j], b4[j]);
#pragma unroll
            for (int i = 0; i < 4; i++) {
                unsigned long long ap = pack2(a8[2 * i], a8[2 * i + 1]);
#pragma unroll
                for (int j = 0; j < 4; j++) ffma2(acc2[i][j], ap, bp[j]);
            }
        }
        __syncthreads();
    }

#pragma unroll
    for (int i = 0; i < 4; i++) {
        float lo[4], hi[4];
#pragma unroll
        for (int j = 0; j < 4; j++) unpack2(acc2[i][j], lo[j], hi[j]);
        float4 o0; o0.x = lo[0]; o0.y = lo[1]; o0.z = lo[2]; o0.w = lo[3];
        float4 o1; o1.x = hi[0]; o1.y = hi[1]; o1.z = hi[2]; o1.w = hi[3];
        const int r = row0 + ty * 8 + 2 * i;
        *(float4*)&g_h[(size_t)(r + 0) * DOUTq + col0 + tx * 4] = o0;
        *(float4*)&g_h[(size_t)(r + 1) * DOUTq + col0 + tx * 4] = o1;
    }
}

// =====================================================================
// Kernel 2: per-(row,head) scores via warp dot products
// =====================================================================
__global__ __launch_bounds__(256) void score_kernel(const float* __restrict__ a_src,
                                                    const float* __restrict__ a_dst) {
    const int task = blockIdx.x * 8 + (threadIdx.x >> 5);   // row*4 + head
    const int ln = threadIdx.x & 31;
    const int row = task >> 2;
    const int head = task & 3;

    const float* hp = g_h + (size_t)row * DOUTq + head * HDq;
    float v0 = hp[ln], v1 = hp[ln + 32];
    float s1 = v0 * a_src[head * HDq + ln] + v1 * a_src[head * HDq + ln + 32];
    float s2 = v0 * a_dst[head * HDq + ln] + v1 * a_dst[head * HDq + ln + 32];
#pragma unroll
    for (int off = 16; off > 0; off >>= 1) {
        s1 += __shfl_xor_sync(0xFFFFFFFFu, s1, off);
        s2 += __shfl_xor_sync(0xFFFFFFFFu, s2, off);
    }
    if (ln == 0) {
        g_ssrc[task] = s1;
        g_sdst[task] = s2;
    }
}

// =====================================================================
// Kernel 3: tensor-core aggregation (tf32 mma) + fused softmax denom.
// Block = 256 thr / 8 warps, i-tile = 32 rows, grid (N/32, B).
// Warp w = (head = w&3, nhalf = w>>2): m=32 rows, n=32 cols of its head.
// Per 32-j chunk:
//   P-phase: warp w computes P rows w*4..w*4+3 for ALL heads, stores tf32
//            to double-buffered smem.
//   B-prefetch: the chunk's ENTIRE 32-LDG B tile (h rows, independent of P)
//            is issued BEFORE the barrier -> latency rides under the
//            barrier wait + other warps' P-phases (MLP=32).
//   adj/sdst for the next chunk prefetched likewise.
//   mma-phase: cvt prefetched B, LDS A frags, 10 mma per kk-step
//   (incl. ones-mma giving the softmax denominator in-core).
// =====================================================================
__global__ __launch_bounds__(256, 2) void agg_mma_kernel(const float* __restrict__ adj,
                                                         float* __restrict__ out) {
    __shared__ uint32_t sP[2][Hq][32][36];   // tf32 alpha, double buffered (36.9 KB)
    __shared__ float sS[32][4];              // ssrc rows of this i-tile

    const int t = threadIdx.x;
    const int w = t >> 5;
    const int lane = t & 31;
    const int head = w & 3;
    const int nh = w >> 2;         // n-half: 0 or 1
    const int g = lane >> 2;       // groupID
    const int ct = lane & 3;       // thread-in-group
    const int b = blockIdx.y;
    const int i0 = blockIdx.x * 32;
    const int bN = b * Nq;

    if (t < 32)
        *(float4*)&sS[t][0] = *(const float4*)&g_ssrc[(size_t)(bN + i0 + t) * 4];
    __syncthreads();

    float d[2][4][4];              // [m16 sub][n8 tile][frag]
    float dones[2][4];
#pragma unroll
    for (int s = 0; s < 2; s++) {
#pragma unroll
        for (int nt = 0; nt < 4; nt++)
#pragma unroll
            for (int q = 0; q < 4; q++) d[s][nt][q] = 0.f;
#pragma unroll
        for (int q = 0; q < 4; q++) dones[s][q] = 0.f;
    }

    uint32_t bones[2];
    bones[0] = bones[1] = (g == 0) ? __float_as_uint(1.0f) : 0u;

    const float* hcolbase = g_h + (size_t)bN * DOUTq + head * HDq + nh * 32;
    const float* adjbase = adj + (size_t)(bN + i0 + w * 4) * Nq;

    // prologue: chunk 0 adj/sdst
    float av[4];
    float4 sd4;
    sd4 = __ldg((const float4*)&g_sdst[(size_t)(bN + lane) * 4]);
#pragma unroll
    for (int r = 0; r < 4; r++)
        av[r] = __ldg(adjbase + (size_t)r * Nq + lane);

    for (int c = 0; c < Nq / 32; c++) {
        const int j0 = c * 32;
        const int buf = c & 1;

        // ---------- P-phase: rows w*4 .. w*4+3, all 4 heads ----------
#pragma unroll
        for (int r = 0; r < 4; r++) {
            const int row = w * 4 + r;
            float avr = av[r];
            float4 ss = *(const float4*)&sS[row][0];
            float e0 = ss.x + sd4.x; e0 = fmaxf(e0, NEG_SLOPE * e0);
            float e1 = ss.y + sd4.y; e1 = fmaxf(e1, NEG_SLOPE * e1);
            float e2 = ss.z + sd4.z; e2 = fmaxf(e2, NEG_SLOPE * e2);
            float e3 = ss.w + sd4.w; e3 = fmaxf(e3, NEG_SLOPE * e3);
            sP[buf][0][row][lane] = f2tf32(avr * __expf(e0));
            sP[buf][1][row][lane] = f2tf32(avr * __expf(e1));
            sP[buf][2][row][lane] = f2tf32(avr * __expf(e2));
            sP[buf][3][row][lane] = f2tf32(avr * __expf(e3));
        }

        // ---------- B prefetch for THIS chunk (independent of P, pre-barrier:
        //            32 LDGs in flight across the barrier wait) ----------
        float braw[4][4][2];
        {
            const float* hc = hcolbase + (size_t)j0 * DOUTq;
#pragma unroll
            for (int kk = 0; kk < 4; kk++) {
                const float* hb = hc + (size_t)(kk * 8 + ct) * DOUTq + g;
#pragma unroll
                for (int nt = 0; nt < 4; nt++) {
                    braw[kk][nt][0] = __ldg(hb + nt * 8);
                    braw[kk][nt][1] = __ldg(hb + 4 * DOUTq + nt * 8);
                }
            }
        }

        // ---------- prefetch next chunk's adj/sdst ----------
        if (c + 1 < Nq / 32) {
            const int j1 = j0 + 32;
            sd4 = __ldg((const float4*)&g_sdst[(size_t)(bN + j1 + lane) * 4]);
#pragma unroll
            for (int r = 0; r < 4; r++)
                av[r] = __ldg(adjbase + (size_t)r * Nq + j1 + lane);
        }
        __syncthreads();

        // ---------- mma-phase: head, n-half ----------
#pragma unroll
        for (int kk = 0; kk < 4; kk++) {
            uint32_t bf[4][2];
#pragma unroll
            for (int nt = 0; nt < 4; nt++) {
                bf[nt][0] = f2tf32(braw[kk][nt][0]);
                bf[nt][1] = f2tf32(braw[kk][nt][1]);
            }
#pragma unroll
            for (int s = 0; s < 2; s++) {
                const int ar = s * 16 + g;
                const int acl = kk * 8 + ct;
                uint32_t af[4];
                af[0] = sP[buf][head][ar][acl];
                af[1] = sP[buf][head][ar + 8][acl];
                af[2] = sP[buf][head][ar][acl + 4];
                af[3] = sP[buf][head][ar + 8][acl + 4];
#pragma unroll
                for (int nt = 0; nt < 4; nt++) mma_tf32(d[s][nt], af, bf[nt]);
                mma_tf32(dones[s], af, bones);
            }
        }
    }

    // ---------- epilogue: normalize and store ----------
#pragma unroll
    for (int s = 0; s < 2; s++) {
        float lA = __shfl_sync(0xFFFFFFFFu, dones[s][0], lane & ~3);
        float lB = __shfl_sync(0xFFFFFFFFu, dones[s][2], lane & ~3);
        float liA = 1.0f / lA;
        float liB = 1.0f / lB;
        const int rowA = i0 + s * 16 + g;
        const int rowB = rowA + 8;
        const int col = head * HDq + nh * 32 + 2 * ct;
#pragma unroll
        for (int nt = 0; nt < 4; nt++) {
            float2 oA; oA.x = d[s][nt][0] * liA; oA.y = d[s][nt][1] * liA;
            float2 oB; oB.x = d[s][nt][2] * liB; oB.y = d[s][nt][3] * liB;
            *(float2*)&out[(size_t)(bN + rowA) * DOUTq + col + nt * 8] = oA;
            *(float2*)&out[(size_t)(bN + rowB) * DOUTq + col + nt * 8] = oB;
        }
    }
}

// =====================================================================
extern "C" void kernel_launch(void* const* d_in, const int* in_sizes, int n_in,
                              void* d_out, int out_size) {
    const float* x     = (const float*)d_in[0];   // [B,N,DIN]
    const float* adj   = (const float*)d_in[1];   // [B,N,N]
    const float* W     = (const float*)d_in[2];   // [DOUT,DIN]
    const float* a_src = (const float*)d_in[3];   // [H,HD]
    const float* a_dst = (const float*)d_in[4];   // [H,HD]
    float* out = (float*)d_out;                   // [B,N,DOUT]

    gemm_xWT_kernel<<<dim3((Bq * Nq) / 128, DOUTq / 64), 256>>>(x, W);
    score_kernel<<<(Bq * Nq * Hq) / 8, 256>>>(a_src, a_dst);
    agg_mma_kernel<<<dim3(Nq / 32, Bq), 256>>>(adj, out);
}